// round 6
// baseline (speedup 1.0000x reference)
#include <cuda_runtime.h>
#include <cuda_bf16.h>
#include <math.h>
#include <stdint.h>

constexpr int B = 2, N = 2048, C = 1024, H = 16, D = 64, DFF = 4096;
constexpr int BNR = B * N;   // 4096
constexpr float EPS = 1e-5f;

// ---------------- low-level helpers (family-generic PTX: no tcgen05) -------
__device__ __forceinline__ uint32_t smem_u32(const void* p) {
    uint32_t a;
    asm("{ .reg .u64 t; cvta.to.shared.u64 t, %1; cvt.u32.u64 %0, t; }" : "=r"(a) : "l"(p));
    return a;
}
__device__ __forceinline__ void cpasync16(uint32_t dst, const void* src) {
    asm volatile("cp.async.cg.shared.global [%0], [%1], 16;" :: "r"(dst), "l"(src));
}
__device__ __forceinline__ void cp_commit() {
    asm volatile("cp.async.commit_group;");
}
template<int Nw>
__device__ __forceinline__ void cp_wait() {
    asm volatile("cp.async.wait_group %0;" :: "n"(Nw));
}
__device__ __forceinline__ void ldsm4(uint32_t* r, uint32_t addr) {
    asm volatile("ldmatrix.sync.aligned.m8n8.x4.shared.b16 {%0,%1,%2,%3}, [%4];"
        : "=r"(r[0]), "=r"(r[1]), "=r"(r[2]), "=r"(r[3]) : "r"(addr));
}
__device__ __forceinline__ void mma16816(float* d, const uint32_t* a, const uint32_t* b) {
    asm volatile("mma.sync.aligned.m16n8k16.row.col.f32.bf16.bf16.f32 "
        "{%0,%1,%2,%3}, {%4,%5,%6,%7}, {%8,%9}, {%0,%1,%2,%3};"
        : "+f"(d[0]), "+f"(d[1]), "+f"(d[2]), "+f"(d[3])
        : "r"(a[0]), "r"(a[1]), "r"(a[2]), "r"(a[3]), "r"(b[0]), "r"(b[1]));
}
__device__ __forceinline__ float gelu_exact(float v) {
    return 0.5f * v * (1.0f + erff(v * 0.70710678118654752f));
}
__device__ __forceinline__ void split2store(__nv_bfloat16* hi, __nv_bfloat16* lo,
                                            float v0, float v1) {
    __nv_bfloat16 h0 = __float2bfloat16(v0), h1 = __float2bfloat16(v1);
    __nv_bfloat162 hh(h0, h1);
    __nv_bfloat162 ll(__float2bfloat16(v0 - __bfloat162float(h0)),
                      __float2bfloat16(v1 - __bfloat162float(h1)));
    *reinterpret_cast<__nv_bfloat162*>(hi) = hh;
    *reinterpret_cast<__nv_bfloat162*>(lo) = ll;
}
__device__ __forceinline__ uint2 cvt_hi2(float4 v) {
    __nv_bfloat162 a(__float2bfloat16(v.x), __float2bfloat16(v.y));
    __nv_bfloat162 b(__float2bfloat16(v.z), __float2bfloat16(v.w));
    return make_uint2(*(uint32_t*)&a, *(uint32_t*)&b);
}
__device__ __forceinline__ uint2 cvt_lo2(float4 v, uint2 hi) {
    __nv_bfloat162 ha = *(__nv_bfloat162*)&hi.x, hb = *(__nv_bfloat162*)&hi.y;
    __nv_bfloat162 a(__float2bfloat16(v.x - __bfloat162float(ha.x)),
                     __float2bfloat16(v.y - __bfloat162float(ha.y)));
    __nv_bfloat162 b(__float2bfloat16(v.z - __bfloat162float(hb.x)),
                     __float2bfloat16(v.w - __bfloat162float(hb.y)));
    return make_uint2(*(uint32_t*)&a, *(uint32_t*)&b);
}

// ---------------- scratch ----------------
#define GA __device__ __align__(256)
GA __nv_bfloat16 g_xnh[BNR * C],      g_xnl[BNR * C];
GA __nv_bfloat16 g_qwh[3 * C * C],    g_qwl[3 * C * C];
GA __nv_bfloat16 g_pwh[C * C],        g_pwl[C * C];
GA __nv_bfloat16 g_f1h[DFF * C],      g_f1l[DFF * C];
GA __nv_bfloat16 g_f2h[C * DFF],      g_f2l[C * DFF];
GA __nv_bfloat16 g_qh[BNR * 3 * C],   g_ql[BNR * 3 * C];
GA __nv_bfloat16 g_vth[B * H * D * N], g_vtl[B * H * D * N];
GA __nv_bfloat16 g_aoh[BNR * C],      g_aol[BNR * C];
GA __nv_bfloat16 g_hh[BNR * DFF],     g_hl[BNR * DFF];
GA float g_x1[BNR * C];

// ---------------- fp32 -> (hi,lo) bf16 split ----------------
__global__ void split_kernel(const float* __restrict__ s, __nv_bfloat16* __restrict__ hi,
                             __nv_bfloat16* __restrict__ lo, int n4) {
    int i = blockIdx.x * 256 + threadIdx.x;
    if (i >= n4) return;
    float4 v = reinterpret_cast<const float4*>(s)[i];
    uint2 h = cvt_hi2(v);
    uint2 l = cvt_lo2(v, h);
    reinterpret_cast<uint2*>(hi)[i] = h;
    reinterpret_cast<uint2*>(lo)[i] = l;
}

// ---------------- LayerNorm -> split ----------------
__global__ void ln_split(const float* __restrict__ x, const float* __restrict__ g,
                         const float* __restrict__ b, __nv_bfloat16* __restrict__ hi,
                         __nv_bfloat16* __restrict__ lo) {
    const int row = blockIdx.x, tid = threadIdx.x;
    const float* xr = x + (size_t)row * C;
    __shared__ float sd[C];
    __shared__ float red[256];
    float ls = 0.f;
    for (int i = tid; i < C; i += 256) { float v = xr[i]; sd[i] = v; ls += v; }
    red[tid] = ls; __syncthreads();
    for (int s = 128; s > 0; s >>= 1) { if (tid < s) red[tid] += red[tid + s]; __syncthreads(); }
    const float mu = red[0] * (1.0f / C); __syncthreads();
    float lv = 0.f;
    for (int i = tid; i < C; i += 256) { float d = sd[i] - mu; lv += d * d; }
    red[tid] = lv; __syncthreads();
    for (int s = 128; s > 0; s >>= 1) { if (tid < s) red[tid] += red[tid + s]; __syncthreads(); }
    const float rstd = rsqrtf(red[0] * (1.0f / C) + EPS);
    for (int i = tid; i < C; i += 256) {
        float v = (sd[i] - mu) * rstd * g[i] + b[i];
        __nv_bfloat16 h = __float2bfloat16(v);
        hi[(size_t)row * C + i] = h;
        lo[(size_t)row * C + i] = __float2bfloat16(v - __bfloat162float(h));
    }
}

// ---------------- masked softmax (in-place fp32) ----------------
__global__ void softmax_kernel(float* __restrict__ attn, const int* __restrict__ mask) {
    const long long row = blockIdx.x;
    const int b = (int)(row / ((long long)H * N));
    float* p = attn + row * (long long)N;
    const int* mr = mask + (size_t)b * N;
    const int tid = threadIdx.x;
    __shared__ float red[256];
    float vals[8];
    float lmax = -INFINITY;
    #pragma unroll
    for (int j = 0; j < 8; j++) {
        int i = tid + j * 256;
        float v = mr[i] ? p[i] : -INFINITY;
        vals[j] = v; lmax = fmaxf(lmax, v);
    }
    red[tid] = lmax; __syncthreads();
    for (int s = 128; s > 0; s >>= 1) { if (tid < s) red[tid] = fmaxf(red[tid], red[tid + s]); __syncthreads(); }
    const float rm = red[0]; __syncthreads();
    float ls = 0.f;
    #pragma unroll
    for (int j = 0; j < 8; j++) { float e = __expf(vals[j] - rm); vals[j] = e; ls += e; }
    red[tid] = ls; __syncthreads();
    for (int s = 128; s > 0; s >>= 1) { if (tid < s) red[tid] += red[tid + s]; __syncthreads(); }
    const float inv = 1.0f / red[0];
    #pragma unroll
    for (int j = 0; j < 8; j++) p[tid + j * 256] = vals[j] * inv;
}

// ---------------- V transpose: qkv[.,2C+h*64+d] -> vt[b,h,d,n] ----------------
__global__ void vtrans(const __nv_bfloat16* __restrict__ qh, const __nv_bfloat16* __restrict__ ql,
                       __nv_bfloat16* __restrict__ vh, __nv_bfloat16* __restrict__ vl) {
    const int z = blockIdx.z, b = z >> 4, h = z & 15;
    const int n0 = blockIdx.x * 32, tid = threadIdx.x;
    __shared__ __nv_bfloat16 sh[64][33], sl[64][33];
    for (int i = tid; i < 2048; i += 256) {
        int r = i >> 6, d = i & 63;
        size_t o = (size_t)(b * N + n0 + r) * (3 * C) + 2 * C + h * 64 + d;
        sh[d][r] = qh[o]; sl[d][r] = ql[o];
    }
    __syncthreads();
    for (int i = tid; i < 2048; i += 256) {
        int d = i >> 5, c = i & 31;
        size_t o = (size_t)z * D * N + (size_t)d * N + n0 + c;
        vh[o] = sh[d][c]; vl[o] = sl[d][c];
    }
}

// ===========================================================================
// HMMA GEMM (NT), 3-stage cp.async ring, BK=32, CTA tile 128 x BN_, 8 warps.
// EPI: 0 = *0.125 -> fp32   1 = split -> hi/lo   2 = +bias+resid -> fp32
//      3 = gelu(+bias) -> split hi/lo
// ===========================================================================
template<int BN_, int EPI>
__global__ void __launch_bounds__(256, 1) hgemm(
    const __nv_bfloat16* __restrict__ Ah, const __nv_bfloat16* __restrict__ Al,
    int lda, long long sAb, long long sAh,
    const __nv_bfloat16* __restrict__ Bh, const __nv_bfloat16* __restrict__ Bl,
    int ldb, long long sBb, long long sBh,
    float* __restrict__ Cf, __nv_bfloat16* __restrict__ Chi, __nv_bfloat16* __restrict__ Clo,
    int ldc, long long sCb, long long sCh,
    int K, const float* __restrict__ bias, const float* __restrict__ resid) {
    extern __shared__ char smem[];
    constexpr int ROWB = 80;
    constexpr int ATILE = 128 * ROWB;
    constexpr int STAGE = 2 * ATILE + 2 * BN_ * ROWB;
    constexpr int WTN = BN_ / 2;
    constexpr int NA = WTN / 8;

    const int tid = threadIdx.x, lane = tid & 31, wid = tid >> 5;
    const int wm = wid & 3, wn = wid >> 2;
    const int z = blockIdx.z, bz = z >> 4, hz = z & 15;
    Ah += (size_t)bz * sAb + (size_t)hz * sAh;
    Al += (size_t)bz * sAb + (size_t)hz * sAh;
    Bh += (size_t)bz * sBb + (size_t)hz * sBh;
    Bl += (size_t)bz * sBb + (size_t)hz * sBh;
    const size_t coff = (size_t)bz * sCb + (size_t)hz * sCh;
    const int m0 = blockIdx.y * 128, n0 = blockIdx.x * BN_;
    const uint32_t sbase = smem_u32(smem);

    auto load_stage = [&](int s, int k0) {
        const uint32_t st = sbase + s * STAGE;
        #pragma unroll
        for (int i = tid; i < 512; i += 256) {
            int r = i >> 2, c4 = i & 3;
            uint32_t d = st + r * ROWB + c4 * 16;
            cpasync16(d,         Ah + (size_t)(m0 + r) * lda + k0 + c4 * 8);
            cpasync16(d + ATILE, Al + (size_t)(m0 + r) * lda + k0 + c4 * 8);
        }
        #pragma unroll
        for (int i = tid; i < BN_ * 4; i += 256) {
            int r = i >> 2, c4 = i & 3;
            uint32_t d = st + 2 * ATILE + r * ROWB + c4 * 16;
            cpasync16(d,              Bh + (size_t)(n0 + r) * ldb + k0 + c4 * 8);
            cpasync16(d + BN_ * ROWB, Bl + (size_t)(n0 + r) * ldb + k0 + c4 * 8);
        }
        cp_commit();
    };

    float acc[2][NA][4];
    #pragma unroll
    for (int a = 0; a < 2; a++)
        #pragma unroll
        for (int b2 = 0; b2 < NA; b2++)
            #pragma unroll
            for (int c = 0; c < 4; c++) acc[a][b2][c] = 0.f;

    const int nch = K >> 5;
    load_stage(0, 0);
    load_stage(1, 32);

    int s_rd = 0, s_wr = 2;
    for (int ch = 0; ch < nch; ch++) {
        cp_wait<1>();
        __syncthreads();
        if (ch + 2 < nch) {
            load_stage(s_wr, (ch + 2) << 5);
        } else {
            cp_commit();
        }
        const uint32_t st  = sbase + s_rd * STAGE;
        const uint32_t bst = st + 2 * ATILE;
        const int arow = wm * 32 + (lane & 15);
        const int acolb = ((lane >> 4) << 4);
        const int brow = (lane & 7) + ((lane >> 4) << 3);
        const int bcolb = (((lane >> 3) & 1) << 4);
        #pragma unroll
        for (int ks = 0; ks < 2; ks++) {
            uint32_t afh[2][4], afl[2][4];
            #pragma unroll
            for (int ma = 0; ma < 2; ma++) {
                uint32_t ad = st + (arow + ma * 16) * ROWB + ks * 32 + acolb;
                ldsm4(afh[ma], ad);
                ldsm4(afl[ma], ad + ATILE);
            }
            uint32_t bfh[NA][2], bfl[NA][2];
            #pragma unroll
            for (int p = 0; p < NA / 2; p++) {
                uint32_t r4[4];
                uint32_t bd = bst + (wn * WTN + p * 16 + brow) * ROWB + ks * 32 + bcolb;
                ldsm4(r4, bd);
                bfh[2*p][0] = r4[0]; bfh[2*p][1] = r4[1];
                bfh[2*p+1][0] = r4[2]; bfh[2*p+1][1] = r4[3];
                ldsm4(r4, bd + BN_ * ROWB);
                bfl[2*p][0] = r4[0]; bfl[2*p][1] = r4[1];
                bfl[2*p+1][0] = r4[2]; bfl[2*p+1][1] = r4[3];
            }
            #pragma unroll
            for (int ma = 0; ma < 2; ma++)
                #pragma unroll
                for (int na = 0; na < NA; na++) {
                    mma16816(acc[ma][na], afh[ma], bfh[na]);
                    mma16816(acc[ma][na], afh[ma], bfl[na]);
                    mma16816(acc[ma][na], afl[ma], bfh[na]);
                }
        }
        __syncthreads();
        s_rd = (s_rd == 2) ? 0 : s_rd + 1;
        s_wr = (s_wr == 2) ? 0 : s_wr + 1;
    }

    #pragma unroll
    for (int ma = 0; ma < 2; ma++)
        #pragma unroll
        for (int na = 0; na < NA; na++) {
            const int gr0 = m0 + wm * 32 + ma * 16 + (lane >> 2);
            const int gc  = n0 + wn * WTN + na * 8 + ((lane & 3) << 1);
            #pragma unroll
            for (int h2 = 0; h2 < 2; h2++) {
                const int gr = gr0 + h2 * 8;
                float v0 = acc[ma][na][h2 * 2], v1 = acc[ma][na][h2 * 2 + 1];
                const size_t o = coff + (size_t)gr * ldc + gc;
                if (EPI == 0) {
                    *reinterpret_cast<float2*>(Cf + o) = make_float2(v0 * 0.125f, v1 * 0.125f);
                }
                if (EPI == 1) split2store(Chi + o, Clo + o, v0, v1);
                if (EPI == 2) {
                    *reinterpret_cast<float2*>(Cf + o) = make_float2(
                        v0 + bias[gc]     + resid[(size_t)gr * ldc + gc],
                        v1 + bias[gc + 1] + resid[(size_t)gr * ldc + gc + 1]);
                }
                if (EPI == 3) {
                    float t0 = gelu_exact(v0 + bias[gc]);
                    float t1 = gelu_exact(v1 + bias[gc + 1]);
                    split2store(Chi + o, Clo + o, t0, t1);
                }
            }
        }
}

// ===========================================================================
// attn @ V: A = attn fp32 [N,N] per head (converted to bf16 hi/lo in-kernel),
// B = vt bf16 hi/lo [D,N]. CTA: 128 rows x 64 cols, K=2048, BK=32. 3-stage.
// Output: split hi/lo into ao[b*N + row, h*64 + col].
// ===========================================================================
__global__ void __launch_bounds__(256, 1) av_gemm(
    const float* __restrict__ attn,
    const __nv_bfloat16* __restrict__ Vh, const __nv_bfloat16* __restrict__ Vl,
    __nv_bfloat16* __restrict__ Ohi, __nv_bfloat16* __restrict__ Olo) {
    extern __shared__ char smem[];
    constexpr int ROWB = 80;
    constexpr int ATILE = 128 * ROWB;          // 10240 (one of hi/lo)
    constexpr int BTILE = 64 * ROWB;           // 5120
    constexpr int STAGE = 2 * ATILE + 2 * BTILE;  // 30720
    constexpr int NA = 4;                      // warp n-tile 32 -> 4 atoms

    const int tid = threadIdx.x, lane = tid & 31, wid = tid >> 5;
    const int wm = wid & 3, wn = wid >> 2;
    const int z = blockIdx.z, bz = z >> 4, hz = z & 15;
    const int m0 = blockIdx.x * 128;
    const float* Ab = attn + (size_t)z * N * N;
    const __nv_bfloat16* Bh = Vh + (size_t)z * D * N;
    const __nv_bfloat16* Bl = Vl + (size_t)z * D * N;
    const uint32_t sbase = smem_u32(smem);

    // A regs: 4 float4 per thread per stage (128x32 fp32)
    float4 areg[4];
    auto ldg_A = [&](int k0) {
        #pragma unroll
        for (int j = 0; j < 4; j++) {
            int i = tid + j * 256;
            int r = i >> 3, c4 = i & 7;
            areg[j] = *reinterpret_cast<const float4*>(Ab + (size_t)(m0 + r) * N + k0 + c4 * 4);
        }
    };
    auto sts_A = [&](int s) {
        const uint32_t st = sbase + s * STAGE;
        #pragma unroll
        for (int j = 0; j < 4; j++) {
            int i = tid + j * 256;
            int r = i >> 3, c4 = i & 7;
            uint2 h = cvt_hi2(areg[j]);
            uint2 l = cvt_lo2(areg[j], h);
            *reinterpret_cast<uint2*>(smem + s * STAGE + r * ROWB + c4 * 8) = h;
            *reinterpret_cast<uint2*>(smem + s * STAGE + ATILE + r * ROWB + c4 * 8) = l;
        }
        (void)st;
    };
    auto ld_B = [&](int s, int k0) {
        const uint32_t st = sbase + s * STAGE + 2 * ATILE;
        #pragma unroll
        for (int i = tid; i < 256; i += 256) {
            int r = i >> 2, c4 = i & 3;
            uint32_t d = st + r * ROWB + c4 * 16;
            cpasync16(d,         Bh + (size_t)r * N + k0 + c4 * 8);
            cpasync16(d + BTILE, Bl + (size_t)r * N + k0 + c4 * 8);
        }
        cp_commit();
    };

    float acc[2][NA][4];
    #pragma unroll
    for (int a = 0; a < 2; a++)
        #pragma unroll
        for (int b2 = 0; b2 < NA; b2++)
            #pragma unroll
            for (int c = 0; c < 4; c++) acc[a][b2][c] = 0.f;

    constexpr int nch = N / 32;    // 64
    ldg_A(0); sts_A(0); ld_B(0, 0);
    ldg_A(32); ld_B(1, 32);

    int s_rd = 0, s_wr1 = 1, s_wr2 = 2;
    for (int ch = 0; ch < nch; ch++) {
        cp_wait<1>();
        __syncthreads();
        if (ch + 1 < nch) sts_A(s_wr1);            // A(ch+1) from regs
        if (ch + 2 < nch) {
            ldg_A((ch + 2) << 5);
            ld_B(s_wr2, (ch + 2) << 5);
        } else {
            cp_commit();
        }
        const uint32_t st  = sbase + s_rd * STAGE;
        const uint32_t bst = st + 2 * ATILE;
        const int arow = wm * 32 + (lane & 15);
        const int acolb = ((lane >> 4) << 4);
        const int brow = (lane & 7) + ((lane >> 4) << 3);
        const int bcolb = (((lane >> 3) & 1) << 4);
        #pragma unroll
        for (int ks = 0; ks < 2; ks++) {
            uint32_t afh[2][4], afl[2][4];
            #pragma unroll
            for (int ma = 0; ma < 2; ma++) {
                uint32_t ad = st + (arow + ma * 16) * ROWB + ks * 32 + acolb;
                ldsm4(afh[ma], ad);
                ldsm4(afl[ma], ad + ATILE);
            }
            uint32_t bfh[NA][2], bfl[NA][2];
            #pragma unroll
            for (int p = 0; p < NA / 2; p++) {
                uint32_t r4[4];
                uint32_t bd = bst + (wn * 32 + p * 16 + brow) * ROWB + ks * 32 + bcolb;
                ldsm4(r4, bd);
                bfh[2*p][0] = r4[0]; bfh[2*p][1] = r4[1];
                bfh[2*p+1][0] = r4[2]; bfh[2*p+1][1] = r4[3];
                ldsm4(r4, bd + BTILE);
                bfl[2*p][0] = r4[0]; bfl[2*p][1] = r4[1];
                bfl[2*p+1][0] = r4[2]; bfl[2*p+1][1] = r4[3];
            }
            #pragma unroll
            for (int ma = 0; ma < 2; ma++)
                #pragma unroll
                for (int na = 0; na < NA; na++) {
                    mma16816(acc[ma][na], afh[ma], bfh[na]);
                    mma16816(acc[ma][na], afh[ma], bfl[na]);
                    mma16816(acc[ma][na], afl[ma], bfh[na]);
                }
        }
        __syncthreads();
        s_rd  = (s_rd  == 2) ? 0 : s_rd  + 1;
        s_wr1 = (s_wr1 == 2) ? 0 : s_wr1 + 1;
        s_wr2 = (s_wr2 == 2) ? 0 : s_wr2 + 1;
    }

    #pragma unroll
    for (int ma = 0; ma < 2; ma++)
        #pragma unroll
        for (int na = 0; na < NA; na++) {
            const int lr0 = wm * 32 + ma * 16 + (lane >> 2);
            const int gc  = hz * 64 + wn * 32 + na * 8 + ((lane & 3) << 1);
            #pragma unroll
            for (int h2 = 0; h2 < 2; h2++) {
                const size_t o = (size_t)(bz * N + m0 + lr0 + h2 * 8) * C + gc;
                split2store(Ohi + o, Olo + o, acc[ma][na][h2 * 2], acc[ma][na][h2 * 2 + 1]);
            }
        }
}

constexpr int SMB128 = 3 * (2 * 128 * 80 + 2 * 128 * 80);  // 122880
constexpr int SMB_AV = 3 * (2 * 128 * 80 + 2 * 64 * 80);   // 92160

// ---------------- host ----------------
extern "C" void kernel_launch(void* const* d_in, const int* in_sizes, int n_in,
                              void* d_out, int out_size) {
    const float* x      = (const float*)d_in[0];
    const int*   mask   = (const int*)  d_in[1];
    const float* qkv_w  = (const float*)d_in[2];
    const float* proj_w = (const float*)d_in[3];
    const float* proj_b = (const float*)d_in[4];
    const float* ln1_g  = (const float*)d_in[5];
    const float* ln1_b  = (const float*)d_in[6];
    const float* ln2_g  = (const float*)d_in[7];
    const float* ln2_b  = (const float*)d_in[8];
    const float* fc1_w  = (const float*)d_in[9];
    const float* fc1_b  = (const float*)d_in[10];
    const float* fc2_w  = (const float*)d_in[11];
    const float* fc2_b  = (const float*)d_in[12];
    float* out_x    = (float*)d_out;
    float* out_attn = out_x + (size_t)B * N * C;

    cudaFuncSetAttribute(hgemm<128,0>, cudaFuncAttributeMaxDynamicSharedMemorySize, SMB128);
    cudaFuncSetAttribute(hgemm<128,1>, cudaFuncAttributeMaxDynamicSharedMemorySize, SMB128);
    cudaFuncSetAttribute(hgemm<128,2>, cudaFuncAttributeMaxDynamicSharedMemorySize, SMB128);
    cudaFuncSetAttribute(hgemm<128,3>, cudaFuncAttributeMaxDynamicSharedMemorySize, SMB128);
    cudaFuncSetAttribute(av_gemm,      cudaFuncAttributeMaxDynamicSharedMemorySize, SMB_AV);

    __nv_bfloat16 *xnh, *xnl, *qwh, *qwl, *pwh, *pwl, *f1h, *f1l, *f2h, *f2l;
    __nv_bfloat16 *qh, *ql, *vth, *vtl, *aoh, *aol, *hh, *hl;
    float* x1;
    cudaGetSymbolAddress((void**)&xnh, g_xnh); cudaGetSymbolAddress((void**)&xnl, g_xnl);
    cudaGetSymbolAddress((void**)&qwh, g_qwh); cudaGetSymbolAddress((void**)&qwl, g_qwl);
    cudaGetSymbolAddress((void**)&pwh, g_pwh); cudaGetSymbolAddress((void**)&pwl, g_pwl);
    cudaGetSymbolAddress((void**)&f1h, g_f1h); cudaGetSymbolAddress((void**)&f1l, g_f1l);
    cudaGetSymbolAddress((void**)&f2h, g_f2h); cudaGetSymbolAddress((void**)&f2l, g_f2l);
    cudaGetSymbolAddress((void**)&qh,  g_qh);  cudaGetSymbolAddress((void**)&ql,  g_ql);
    cudaGetSymbolAddress((void**)&vth, g_vth); cudaGetSymbolAddress((void**)&vtl, g_vtl);
    cudaGetSymbolAddress((void**)&aoh, g_aoh); cudaGetSymbolAddress((void**)&aol, g_aol);
    cudaGetSymbolAddress((void**)&hh,  g_hh);  cudaGetSymbolAddress((void**)&hl,  g_hl);
    cudaGetSymbolAddress((void**)&x1,  g_x1);

    // weight splits
    split_kernel<<<3 * C * C / 4 / 256, 256>>>(qkv_w, qwh, qwl, 3 * C * C / 4);
    split_kernel<<<C * C / 4 / 256, 256>>>(proj_w, pwh, pwl, C * C / 4);
    split_kernel<<<DFF * C / 4 / 256, 256>>>(fc1_w, f1h, f1l, DFF * C / 4);
    split_kernel<<<C * DFF / 4 / 256, 256>>>(fc2_w, f2h, f2l, C * DFF / 4);

    // 1) ln1 -> xn (hi/lo)
    ln_split<<<BNR, 256>>>(x, ln1_g, ln1_b, xnh, xnl);
    // 2) qkv = xn @ qkv_w^T -> split
    hgemm<128,1><<<dim3(24, 32, 1), 256, SMB128>>>(
        xnh, xnl, C, 0, 0, qwh, qwl, C, 0, 0,
        nullptr, qh, ql, 3 * C, 0, 0, C, nullptr, nullptr);
    // 3) scores = 0.125 * Q @ K^T -> out_attn fp32 (batched over B*H)
    hgemm<128,0><<<dim3(16, 16, 32), 256, SMB128>>>(
        qh, ql, 3 * C, (long long)N * 3 * C, 64,
        qh + C, ql + C, 3 * C, (long long)N * 3 * C, 64,
        out_attn, nullptr, nullptr, N, (long long)H * N * N, (long long)N * N,
        64, nullptr, nullptr);
    // 4) masked softmax (in-place, fp32 only)
    softmax_kernel<<<B * H * N, 256>>>(out_attn, mask);
    // 5) V transpose (per-head [D, N] hi/lo)
    vtrans<<<dim3(N / 32, 1, B * H), 256>>>(qh, ql, vth, vtl);
    // 6) ao = attn @ V (reads fp32 attn, converts in-kernel) -> split
    av_gemm<<<dim3(16, 1, 32), 256, SMB_AV>>>(out_attn, vth, vtl, aoh, aol);
    // 7) x1 = x + ao @ proj_w^T + proj_b
    hgemm<128,2><<<dim3(8, 32, 1), 256, SMB128>>>(
        aoh, aol, C, 0, 0, pwh, pwl, C, 0, 0,
        x1, nullptr, nullptr, C, 0, 0, C, proj_b, x);
    // 8) ln2 -> xn (hi/lo)
    ln_split<<<BNR, 256>>>(x1, ln2_g, ln2_b, xnh, xnl);
    // 9) h = gelu(xn @ fc1_w^T + fc1_b) -> split
    hgemm<128,3><<<dim3(32, 32, 1), 256, SMB128>>>(
        xnh, xnl, C, 0, 0, f1h, f1l, C, 0, 0,
        nullptr, hh, hl, DFF, 0, 0, C, fc1_b, nullptr);
    // 10) out_x = x1 + h @ fc2_w^T + fc2_b
    hgemm<128,2><<<dim3(8, 32, 1), 256, SMB128>>>(
        hh, hl, DFF, 0, 0, f2h, f2l, DFF, 0, 0,
        out_x, nullptr, nullptr, C, 0, 0, DFF, fc2_b, x1);
}

// round 7
// speedup vs baseline: 1.5019x; 1.5019x over previous
#include <cuda_runtime.h>
#include <cuda_bf16.h>
#include <math.h>
#include <stdint.h>

constexpr int B = 2, N = 2048, C = 1024, H = 16, D = 64, DFF = 4096;
constexpr int BNR = B * N;   // 4096
constexpr float EPS = 1e-5f;

// ---------------- low-level helpers (family-generic PTX: no tcgen05) -------
__device__ __forceinline__ uint32_t smem_u32(const void* p) {
    uint32_t a;
    asm("{ .reg .u64 t; cvta.to.shared.u64 t, %1; cvt.u32.u64 %0, t; }" : "=r"(a) : "l"(p));
    return a;
}
__device__ __forceinline__ void cpasync16(uint32_t dst, const void* src) {
    asm volatile("cp.async.cg.shared.global [%0], [%1], 16;" :: "r"(dst), "l"(src));
}
__device__ __forceinline__ void cp_commit() {
    asm volatile("cp.async.commit_group;");
}
template<int Nw>
__device__ __forceinline__ void cp_wait() {
    asm volatile("cp.async.wait_group %0;" :: "n"(Nw));
}
__device__ __forceinline__ void ldsm4(uint32_t* r, uint32_t addr) {
    asm volatile("ldmatrix.sync.aligned.m8n8.x4.shared.b16 {%0,%1,%2,%3}, [%4];"
        : "=r"(r[0]), "=r"(r[1]), "=r"(r[2]), "=r"(r[3]) : "r"(addr));
}
__device__ __forceinline__ void mma16816(float* d, const uint32_t* a, const uint32_t* b) {
    asm volatile("mma.sync.aligned.m16n8k16.row.col.f32.bf16.bf16.f32 "
        "{%0,%1,%2,%3}, {%4,%5,%6,%7}, {%8,%9}, {%0,%1,%2,%3};"
        : "+f"(d[0]), "+f"(d[1]), "+f"(d[2]), "+f"(d[3])
        : "r"(a[0]), "r"(a[1]), "r"(a[2]), "r"(a[3]), "r"(b[0]), "r"(b[1]));
}
__device__ __forceinline__ float gelu_exact(float v) {
    return 0.5f * v * (1.0f + erff(v * 0.70710678118654752f));
}
__device__ __forceinline__ void split2store(__nv_bfloat16* hi, __nv_bfloat16* lo,
                                            float v0, float v1) {
    __nv_bfloat16 h0 = __float2bfloat16(v0), h1 = __float2bfloat16(v1);
    __nv_bfloat162 hh(h0, h1);
    __nv_bfloat162 ll(__float2bfloat16(v0 - __bfloat162float(h0)),
                      __float2bfloat16(v1 - __bfloat162float(h1)));
    *reinterpret_cast<__nv_bfloat162*>(hi) = hh;
    *reinterpret_cast<__nv_bfloat162*>(lo) = ll;
}
__device__ __forceinline__ uint2 cvt_hi2(float4 v) {
    __nv_bfloat162 a(__float2bfloat16(v.x), __float2bfloat16(v.y));
    __nv_bfloat162 b(__float2bfloat16(v.z), __float2bfloat16(v.w));
    return make_uint2(*(uint32_t*)&a, *(uint32_t*)&b);
}
__device__ __forceinline__ uint2 cvt_lo2(float4 v, uint2 hi) {
    __nv_bfloat162 ha = *(__nv_bfloat162*)&hi.x, hb = *(__nv_bfloat162*)&hi.y;
    __nv_bfloat162 a(__float2bfloat16(v.x - __bfloat162float(ha.x)),
                     __float2bfloat16(v.y - __bfloat162float(ha.y)));
    __nv_bfloat162 b(__float2bfloat16(v.z - __bfloat162float(hb.x)),
                     __float2bfloat16(v.w - __bfloat162float(hb.y)));
    return make_uint2(*(uint32_t*)&a, *(uint32_t*)&b);
}

// ---------------- scratch ----------------
#define GA __device__ __align__(256)
GA __nv_bfloat16 g_xnh[BNR * C],      g_xnl[BNR * C];
GA __nv_bfloat16 g_qwh[3 * C * C],    g_qwl[3 * C * C];
GA __nv_bfloat16 g_pwh[C * C],        g_pwl[C * C];
GA __nv_bfloat16 g_f1h[DFF * C],      g_f1l[DFF * C];
GA __nv_bfloat16 g_f2h[C * DFF],      g_f2l[C * DFF];
GA __nv_bfloat16 g_qh[BNR * 3 * C],   g_ql[BNR * 3 * C];
GA __nv_bfloat16 g_vth[B * H * D * N], g_vtl[B * H * D * N];
GA __nv_bfloat16 g_aoh[BNR * C],      g_aol[BNR * C];
GA __nv_bfloat16 g_hh[BNR * DFF],     g_hl[BNR * DFF];
GA float g_x1[BNR * C];

// ---------------- fp32 -> (hi,lo) bf16 split ----------------
__global__ void split_kernel(const float* __restrict__ s, __nv_bfloat16* __restrict__ hi,
                             __nv_bfloat16* __restrict__ lo, int n4) {
    int i = blockIdx.x * 256 + threadIdx.x;
    if (i >= n4) return;
    float4 v = reinterpret_cast<const float4*>(s)[i];
    uint2 h = cvt_hi2(v);
    uint2 l = cvt_lo2(v, h);
    reinterpret_cast<uint2*>(hi)[i] = h;
    reinterpret_cast<uint2*>(lo)[i] = l;
}

// ---------------- LayerNorm -> split ----------------
__global__ void ln_split(const float* __restrict__ x, const float* __restrict__ g,
                         const float* __restrict__ b, __nv_bfloat16* __restrict__ hi,
                         __nv_bfloat16* __restrict__ lo) {
    const int row = blockIdx.x, tid = threadIdx.x;
    const float* xr = x + (size_t)row * C;
    __shared__ float sd[C];
    __shared__ float red[256];
    float ls = 0.f;
    for (int i = tid; i < C; i += 256) { float v = xr[i]; sd[i] = v; ls += v; }
    red[tid] = ls; __syncthreads();
    for (int s = 128; s > 0; s >>= 1) { if (tid < s) red[tid] += red[tid + s]; __syncthreads(); }
    const float mu = red[0] * (1.0f / C); __syncthreads();
    float lv = 0.f;
    for (int i = tid; i < C; i += 256) { float d = sd[i] - mu; lv += d * d; }
    red[tid] = lv; __syncthreads();
    for (int s = 128; s > 0; s >>= 1) { if (tid < s) red[tid] += red[tid + s]; __syncthreads(); }
    const float rstd = rsqrtf(red[0] * (1.0f / C) + EPS);
    for (int i = tid; i < C; i += 256) {
        float v = (sd[i] - mu) * rstd * g[i] + b[i];
        __nv_bfloat16 h = __float2bfloat16(v);
        hi[(size_t)row * C + i] = h;
        lo[(size_t)row * C + i] = __float2bfloat16(v - __bfloat162float(h));
    }
}

// ---------------- masked softmax (in-place fp32) ----------------
__global__ void softmax_kernel(float* __restrict__ attn, const int* __restrict__ mask) {
    const long long row = blockIdx.x;
    const int b = (int)(row / ((long long)H * N));
    float* p = attn + row * (long long)N;
    const int* mr = mask + (size_t)b * N;
    const int tid = threadIdx.x;
    __shared__ float red[256];
    float vals[8];
    float lmax = -INFINITY;
    #pragma unroll
    for (int j = 0; j < 8; j++) {
        int i = tid + j * 256;
        float v = mr[i] ? p[i] : -INFINITY;
        vals[j] = v; lmax = fmaxf(lmax, v);
    }
    red[tid] = lmax; __syncthreads();
    for (int s = 128; s > 0; s >>= 1) { if (tid < s) red[tid] = fmaxf(red[tid], red[tid + s]); __syncthreads(); }
    const float rm = red[0]; __syncthreads();
    float ls = 0.f;
    #pragma unroll
    for (int j = 0; j < 8; j++) { float e = __expf(vals[j] - rm); vals[j] = e; ls += e; }
    red[tid] = ls; __syncthreads();
    for (int s = 128; s > 0; s >>= 1) { if (tid < s) red[tid] += red[tid + s]; __syncthreads(); }
    const float inv = 1.0f / red[0];
    #pragma unroll
    for (int j = 0; j < 8; j++) p[tid + j * 256] = vals[j] * inv;
}

// ---------------- V transpose: qkv[.,2C+h*64+d] -> vt[b,h,d,n] ----------------
__global__ void vtrans(const __nv_bfloat16* __restrict__ qh, const __nv_bfloat16* __restrict__ ql,
                       __nv_bfloat16* __restrict__ vh, __nv_bfloat16* __restrict__ vl) {
    const int z = blockIdx.z, b = z >> 4, h = z & 15;
    const int n0 = blockIdx.x * 32, tid = threadIdx.x;
    __shared__ __nv_bfloat16 sh[64][33], sl[64][33];
    for (int i = tid; i < 2048; i += 256) {
        int r = i >> 6, d = i & 63;
        size_t o = (size_t)(b * N + n0 + r) * (3 * C) + 2 * C + h * 64 + d;
        sh[d][r] = qh[o]; sl[d][r] = ql[o];
    }
    __syncthreads();
    for (int i = tid; i < 2048; i += 256) {
        int d = i >> 5, c = i & 31;
        size_t o = (size_t)z * D * N + (size_t)d * N + n0 + c;
        vh[o] = sh[d][c]; vl[o] = sl[d][c];
    }
}

// ===========================================================================
// HMMA GEMM (NT), 2-stage cp.async (R5-proven: 81920 B smem -> 2 CTAs/SM).
// EPI: 0 = *0.125 -> fp32   1 = split -> hi/lo   2 = +bias+resid -> fp32
//      3 = gelu(+bias) -> split hi/lo
// ===========================================================================
template<int BN_, int EPI>
__global__ void __launch_bounds__(256, 1) hgemm(
    const __nv_bfloat16* __restrict__ Ah, const __nv_bfloat16* __restrict__ Al,
    int lda, long long sAb, long long sAh,
    const __nv_bfloat16* __restrict__ Bh, const __nv_bfloat16* __restrict__ Bl,
    int ldb, long long sBb, long long sBh,
    float* __restrict__ Cf, __nv_bfloat16* __restrict__ Chi, __nv_bfloat16* __restrict__ Clo,
    int ldc, long long sCb, long long sCh,
    int K, const float* __restrict__ bias, const float* __restrict__ resid) {
    extern __shared__ char smem[];
    constexpr int ROWB = 80;
    constexpr int ATILE = 128 * ROWB;
    constexpr int STAGE = 2 * ATILE + 2 * BN_ * ROWB;
    constexpr int WTN = BN_ / 2;
    constexpr int NA = WTN / 8;

    const int tid = threadIdx.x, lane = tid & 31, wid = tid >> 5;
    const int wm = wid & 3, wn = wid >> 2;
    const int z = blockIdx.z, bz = z >> 4, hz = z & 15;
    Ah += (size_t)bz * sAb + (size_t)hz * sAh;
    Al += (size_t)bz * sAb + (size_t)hz * sAh;
    Bh += (size_t)bz * sBb + (size_t)hz * sBh;
    Bl += (size_t)bz * sBb + (size_t)hz * sBh;
    const size_t coff = (size_t)bz * sCb + (size_t)hz * sCh;
    const int m0 = blockIdx.y * 128, n0 = blockIdx.x * BN_;
    const uint32_t sbase = smem_u32(smem);

    auto load_stage = [&](int s, int k0) {
        const uint32_t st = sbase + s * STAGE;
        #pragma unroll
        for (int i = tid; i < 512; i += 256) {
            int r = i >> 2, c4 = i & 3;
            uint32_t d = st + r * ROWB + c4 * 16;
            cpasync16(d,         Ah + (size_t)(m0 + r) * lda + k0 + c4 * 8);
            cpasync16(d + ATILE, Al + (size_t)(m0 + r) * lda + k0 + c4 * 8);
        }
        #pragma unroll
        for (int i = tid; i < BN_ * 4; i += 256) {
            int r = i >> 2, c4 = i & 3;
            uint32_t d = st + 2 * ATILE + r * ROWB + c4 * 16;
            cpasync16(d,              Bh + (size_t)(n0 + r) * ldb + k0 + c4 * 8);
            cpasync16(d + BN_ * ROWB, Bl + (size_t)(n0 + r) * ldb + k0 + c4 * 8);
        }
        cp_commit();
    };

    float acc[2][NA][4];
    #pragma unroll
    for (int a = 0; a < 2; a++)
        #pragma unroll
        for (int b2 = 0; b2 < NA; b2++)
            #pragma unroll
            for (int c = 0; c < 4; c++) acc[a][b2][c] = 0.f;

    const int nch = K >> 5;
    load_stage(0, 0);
    for (int ch = 0; ch < nch; ch++) {
        if (ch + 1 < nch) { load_stage((ch + 1) & 1, (ch + 1) << 5); cp_wait<1>(); }
        else cp_wait<0>();
        __syncthreads();

        const uint32_t st  = sbase + (ch & 1) * STAGE;
        const uint32_t bst = st + 2 * ATILE;
        const int arow = wm * 32 + (lane & 15);
        const int acolb = ((lane >> 4) << 4);
        const int brow = (lane & 7) + ((lane >> 4) << 3);
        const int bcolb = (((lane >> 3) & 1) << 4);
        #pragma unroll
        for (int ks = 0; ks < 2; ks++) {
            uint32_t afh[2][4], afl[2][4];
            #pragma unroll
            for (int ma = 0; ma < 2; ma++) {
                uint32_t ad = st + (arow + ma * 16) * ROWB + ks * 32 + acolb;
                ldsm4(afh[ma], ad);
                ldsm4(afl[ma], ad + ATILE);
            }
            uint32_t bfh[NA][2], bfl[NA][2];
            #pragma unroll
            for (int p = 0; p < NA / 2; p++) {
                uint32_t r4[4];
                uint32_t bd = bst + (wn * WTN + p * 16 + brow) * ROWB + ks * 32 + bcolb;
                ldsm4(r4, bd);
                bfh[2*p][0] = r4[0]; bfh[2*p][1] = r4[1];
                bfh[2*p+1][0] = r4[2]; bfh[2*p+1][1] = r4[3];
                ldsm4(r4, bd + BN_ * ROWB);
                bfl[2*p][0] = r4[0]; bfl[2*p][1] = r4[1];
                bfl[2*p+1][0] = r4[2]; bfl[2*p+1][1] = r4[3];
            }
            #pragma unroll
            for (int ma = 0; ma < 2; ma++)
                #pragma unroll
                for (int na = 0; na < NA; na++) {
                    mma16816(acc[ma][na], afh[ma], bfh[na]);
                    mma16816(acc[ma][na], afh[ma], bfl[na]);
                    mma16816(acc[ma][na], afl[ma], bfh[na]);
                }
        }
        __syncthreads();
    }

    #pragma unroll
    for (int ma = 0; ma < 2; ma++)
        #pragma unroll
        for (int na = 0; na < NA; na++) {
            const int gr0 = m0 + wm * 32 + ma * 16 + (lane >> 2);
            const int gc  = n0 + wn * WTN + na * 8 + ((lane & 3) << 1);
            #pragma unroll
            for (int h2 = 0; h2 < 2; h2++) {
                const int gr = gr0 + h2 * 8;
                float v0 = acc[ma][na][h2 * 2], v1 = acc[ma][na][h2 * 2 + 1];
                const size_t o = coff + (size_t)gr * ldc + gc;
                if (EPI == 0) {
                    *reinterpret_cast<float2*>(Cf + o) = make_float2(v0 * 0.125f, v1 * 0.125f);
                }
                if (EPI == 1) split2store(Chi + o, Clo + o, v0, v1);
                if (EPI == 2) {
                    *reinterpret_cast<float2*>(Cf + o) = make_float2(
                        v0 + bias[gc]     + resid[(size_t)gr * ldc + gc],
                        v1 + bias[gc + 1] + resid[(size_t)gr * ldc + gc + 1]);
                }
                if (EPI == 3) {
                    float t0 = gelu_exact(v0 + bias[gc]);
                    float t1 = gelu_exact(v1 + bias[gc + 1]);
                    split2store(Chi + o, Clo + o, t0, t1);
                }
            }
        }
}

// ===========================================================================
// attn @ V: A = fp32 attn [N,N] per head, converted to bf16 hi/lo in regs
// while staging to SMEM. 2-stage (61440 B smem -> 3 CTAs/SM). B = vt [D,N].
// CTA: 128 rows x 64 cols, K=2048, BK=32. Output: split hi/lo.
// ===========================================================================
__global__ void __launch_bounds__(256, 1) av_gemm(
    const float* __restrict__ attn,
    const __nv_bfloat16* __restrict__ Vh, const __nv_bfloat16* __restrict__ Vl,
    __nv_bfloat16* __restrict__ Ohi, __nv_bfloat16* __restrict__ Olo) {
    extern __shared__ char smem[];
    constexpr int ROWB = 80;
    constexpr int ATILE = 128 * ROWB;             // 10240
    constexpr int BTILE = 64 * ROWB;              // 5120
    constexpr int STAGE = 2 * ATILE + 2 * BTILE;  // 30720
    constexpr int NA = 4;

    const int tid = threadIdx.x, lane = tid & 31, wid = tid >> 5;
    const int wm = wid & 3, wn = wid >> 2;
    const int z = blockIdx.z, bz = z >> 4, hz = z & 15;
    const int m0 = blockIdx.x * 128;
    const float* Ab = attn + (size_t)z * N * N;
    const __nv_bfloat16* Bh = Vh + (size_t)z * D * N;
    const __nv_bfloat16* Bl = Vl + (size_t)z * D * N;
    const uint32_t sbase = smem_u32(smem);

    float4 areg[4];
    auto ldg_A = [&](int k0) {
        #pragma unroll
        for (int j = 0; j < 4; j++) {
            int i = tid + j * 256;
            int r = i >> 3, c4 = i & 7;
            areg[j] = *reinterpret_cast<const float4*>(Ab + (size_t)(m0 + r) * N + k0 + c4 * 4);
        }
    };
    auto sts_A = [&](int s) {
        #pragma unroll
        for (int j = 0; j < 4; j++) {
            int i = tid + j * 256;
            int r = i >> 3, c4 = i & 7;
            uint2 h = cvt_hi2(areg[j]);
            uint2 l = cvt_lo2(areg[j], h);
            *reinterpret_cast<uint2*>(smem + s * STAGE + r * ROWB + c4 * 8) = h;
            *reinterpret_cast<uint2*>(smem + s * STAGE + ATILE + r * ROWB + c4 * 8) = l;
        }
    };
    auto ld_B = [&](int s, int k0) {
        const uint32_t st = sbase + s * STAGE + 2 * ATILE;
        {
            int i = tid;
            int r = i >> 2, c4 = i & 3;
            uint32_t d = st + r * ROWB + c4 * 16;
            cpasync16(d,         Bh + (size_t)r * N + k0 + c4 * 8);
            cpasync16(d + BTILE, Bl + (size_t)r * N + k0 + c4 * 8);
        }
        cp_commit();
    };

    float acc[2][NA][4];
    #pragma unroll
    for (int a = 0; a < 2; a++)
        #pragma unroll
        for (int b2 = 0; b2 < NA; b2++)
            #pragma unroll
            for (int c = 0; c < 4; c++) acc[a][b2][c] = 0.f;

    constexpr int nch = N / 32;    // 64
    ldg_A(0);
    sts_A(0);
    ld_B(0, 0);
    ldg_A(32);                     // regs now hold A(1)

    for (int ch = 0; ch < nch; ch++) {
        if (ch + 1 < nch) {
            sts_A((ch + 1) & 1);   // A(ch+1) from regs (buffer last read at ch-1)
            ld_B((ch + 1) & 1, (ch + 1) << 5);
        }
        if (ch + 2 < nch) ldg_A((ch + 2) << 5);
        if (ch + 1 < nch) cp_wait<1>(); else cp_wait<0>();
        __syncthreads();

        const uint32_t st  = sbase + (ch & 1) * STAGE;
        const uint32_t bst = st + 2 * ATILE;
        const int arow = wm * 32 + (lane & 15);
        const int acolb = ((lane >> 4) << 4);
        const int brow = (lane & 7) + ((lane >> 4) << 3);
        const int bcolb = (((lane >> 3) & 1) << 4);
        #pragma unroll
        for (int ks = 0; ks < 2; ks++) {
            uint32_t afh[2][4], afl[2][4];
            #pragma unroll
            for (int ma = 0; ma < 2; ma++) {
                uint32_t ad = st + (arow + ma * 16) * ROWB + ks * 32 + acolb;
                ldsm4(afh[ma], ad);
                ldsm4(afl[ma], ad + ATILE);
            }
            uint32_t bfh[NA][2], bfl[NA][2];
            #pragma unroll
            for (int p = 0; p < NA / 2; p++) {
                uint32_t r4[4];
                uint32_t bd = bst + (wn * 32 + p * 16 + brow) * ROWB + ks * 32 + bcolb;
                ldsm4(r4, bd);
                bfh[2*p][0] = r4[0]; bfh[2*p][1] = r4[1];
                bfh[2*p+1][0] = r4[2]; bfh[2*p+1][1] = r4[3];
                ldsm4(r4, bd + BTILE);
                bfl[2*p][0] = r4[0]; bfl[2*p][1] = r4[1];
                bfl[2*p+1][0] = r4[2]; bfl[2*p+1][1] = r4[3];
            }
            #pragma unroll
            for (int ma = 0; ma < 2; ma++)
                #pragma unroll
                for (int na = 0; na < NA; na++) {
                    mma16816(acc[ma][na], afh[ma], bfh[na]);
                    mma16816(acc[ma][na], afh[ma], bfl[na]);
                    mma16816(acc[ma][na], afl[ma], bfh[na]);
                }
        }
        __syncthreads();
    }

    #pragma unroll
    for (int ma = 0; ma < 2; ma++)
        #pragma unroll
        for (int na = 0; na < NA; na++) {
            const int lr0 = wm * 32 + ma * 16 + (lane >> 2);
            const int gc  = hz * 64 + wn * 32 + na * 8 + ((lane & 3) << 1);
            #pragma unroll
            for (int h2 = 0; h2 < 2; h2++) {
                const size_t o = (size_t)(bz * N + m0 + lr0 + h2 * 8) * C + gc;
                split2store(Ohi + o, Olo + o, acc[ma][na][h2 * 2], acc[ma][na][h2 * 2 + 1]);
            }
        }
}

constexpr int SMB128 = 2 * (2 * 128 * 80 + 2 * 128 * 80);  // 81920 -> 2 CTAs/SM
constexpr int SMB_AV = 2 * (2 * 128 * 80 + 2 * 64 * 80);   // 61440 -> 3 CTAs/SM

// ---------------- host ----------------
extern "C" void kernel_launch(void* const* d_in, const int* in_sizes, int n_in,
                              void* d_out, int out_size) {
    const float* x      = (const float*)d_in[0];
    const int*   mask   = (const int*)  d_in[1];
    const float* qkv_w  = (const float*)d_in[2];
    const float* proj_w = (const float*)d_in[3];
    const float* proj_b = (const float*)d_in[4];
    const float* ln1_g  = (const float*)d_in[5];
    const float* ln1_b  = (const float*)d_in[6];
    const float* ln2_g  = (const float*)d_in[7];
    const float* ln2_b  = (const float*)d_in[8];
    const float* fc1_w  = (const float*)d_in[9];
    const float* fc1_b  = (const float*)d_in[10];
    const float* fc2_w  = (const float*)d_in[11];
    const float* fc2_b  = (const float*)d_in[12];
    float* out_x    = (float*)d_out;
    float* out_attn = out_x + (size_t)B * N * C;

    cudaFuncSetAttribute(hgemm<128,0>, cudaFuncAttributeMaxDynamicSharedMemorySize, SMB128);
    cudaFuncSetAttribute(hgemm<128,1>, cudaFuncAttributeMaxDynamicSharedMemorySize, SMB128);
    cudaFuncSetAttribute(hgemm<128,2>, cudaFuncAttributeMaxDynamicSharedMemorySize, SMB128);
    cudaFuncSetAttribute(hgemm<128,3>, cudaFuncAttributeMaxDynamicSharedMemorySize, SMB128);
    cudaFuncSetAttribute(av_gemm,      cudaFuncAttributeMaxDynamicSharedMemorySize, SMB_AV);

    __nv_bfloat16 *xnh, *xnl, *qwh, *qwl, *pwh, *pwl, *f1h, *f1l, *f2h, *f2l;
    __nv_bfloat16 *qh, *ql, *vth, *vtl, *aoh, *aol, *hh, *hl;
    float* x1;
    cudaGetSymbolAddress((void**)&xnh, g_xnh); cudaGetSymbolAddress((void**)&xnl, g_xnl);
    cudaGetSymbolAddress((void**)&qwh, g_qwh); cudaGetSymbolAddress((void**)&qwl, g_qwl);
    cudaGetSymbolAddress((void**)&pwh, g_pwh); cudaGetSymbolAddress((void**)&pwl, g_pwl);
    cudaGetSymbolAddress((void**)&f1h, g_f1h); cudaGetSymbolAddress((void**)&f1l, g_f1l);
    cudaGetSymbolAddress((void**)&f2h, g_f2h); cudaGetSymbolAddress((void**)&f2l, g_f2l);
    cudaGetSymbolAddress((void**)&qh,  g_qh);  cudaGetSymbolAddress((void**)&ql,  g_ql);
    cudaGetSymbolAddress((void**)&vth, g_vth); cudaGetSymbolAddress((void**)&vtl, g_vtl);
    cudaGetSymbolAddress((void**)&aoh, g_aoh); cudaGetSymbolAddress((void**)&aol, g_aol);
    cudaGetSymbolAddress((void**)&hh,  g_hh);  cudaGetSymbolAddress((void**)&hl,  g_hl);
    cudaGetSymbolAddress((void**)&x1,  g_x1);

    // weight splits
    split_kernel<<<3 * C * C / 4 / 256, 256>>>(qkv_w, qwh, qwl, 3 * C * C / 4);
    split_kernel<<<C * C / 4 / 256, 256>>>(proj_w, pwh, pwl, C * C / 4);
    split_kernel<<<DFF * C / 4 / 256, 256>>>(fc1_w, f1h, f1l, DFF * C / 4);
    split_kernel<<<C * DFF / 4 / 256, 256>>>(fc2_w, f2h, f2l, C * DFF / 4);

    // 1) ln1 -> xn (hi/lo)
    ln_split<<<BNR, 256>>>(x, ln1_g, ln1_b, xnh, xnl);
    // 2) qkv = xn @ qkv_w^T -> split
    hgemm<128,1><<<dim3(24, 32, 1), 256, SMB128>>>(
        xnh, xnl, C, 0, 0, qwh, qwl, C, 0, 0,
        nullptr, qh, ql, 3 * C, 0, 0, C, nullptr, nullptr);
    // 3) scores = 0.125 * Q @ K^T -> out_attn fp32 (batched over B*H)
    hgemm<128,0><<<dim3(16, 16, 32), 256, SMB128>>>(
        qh, ql, 3 * C, (long long)N * 3 * C, 64,
        qh + C, ql + C, 3 * C, (long long)N * 3 * C, 64,
        out_attn, nullptr, nullptr, N, (long long)H * N * N, (long long)N * N,
        64, nullptr, nullptr);
    // 4) masked softmax (in-place, fp32 only)
    softmax_kernel<<<B * H * N, 256>>>(out_attn, mask);
    // 5) V transpose (per-head [D, N] hi/lo)
    vtrans<<<dim3(N / 32, 1, B * H), 256>>>(qh, ql, vth, vtl);
    // 6) ao = attn @ V (reads fp32 attn, converts in-kernel) -> split
    av_gemm<<<dim3(16, 1, 32), 256, SMB_AV>>>(out_attn, vth, vtl, aoh, aol);
    // 7) x1 = x + ao @ proj_w^T + proj_b
    hgemm<128,2><<<dim3(8, 32, 1), 256, SMB128>>>(
        aoh, aol, C, 0, 0, pwh, pwl, C, 0, 0,
        x1, nullptr, nullptr, C, 0, 0, C, proj_b, x);
    // 8) ln2 -> xn (hi/lo)
    ln_split<<<BNR, 256>>>(x1, ln2_g, ln2_b, xnh, xnl);
    // 9) h = gelu(xn @ fc1_w^T + fc1_b) -> split
    hgemm<128,3><<<dim3(32, 32, 1), 256, SMB128>>>(
        xnh, xnl, C, 0, 0, f1h, f1l, C, 0, 0,
        nullptr, hh, hl, DFF, 0, 0, C, fc1_b, nullptr);
    // 10) out_x = x1 + h @ fc2_w^T + fc2_b
    hgemm<128,2><<<dim3(8, 32, 1), 256, SMB128>>>(
        hh, hl, DFF, 0, 0, f2h, f2l, DFF, 0, 0,
        out_x, nullptr, nullptr, C, 0, 0, DFF, fc2_b, x1);
}